// round 2
// baseline (speedup 1.0000x reference)
#include <cuda_runtime.h>
#include <cuda_bf16.h>
#include <math.h>

// ----------------------------------------------------------------------------
// Problem constants
// ----------------------------------------------------------------------------
#define BATCH   2
#define SEQ     2048
#define TOK     (BATCH * SEQ)        // 4096 rows
#define DMODEL  1024
#define DFF     4096
#define NHEADS  16
#define HDIM    64                   // head dim
#define LN_EPS  1e-5f

// ----------------------------------------------------------------------------
// Scratch buffers (static device allocations; no cudaMalloc allowed)
// ----------------------------------------------------------------------------
__device__ float g_q   [TOK * DMODEL];
__device__ float g_k   [TOK * DMODEL];
__device__ float g_v   [TOK * DMODEL];
__device__ float g_attn[TOK * DMODEL];
__device__ float g_tmp [TOK * DMODEL];
__device__ float g_y1  [TOK * DMODEL];
__device__ float g_y2  [TOK * DMODEL];
__device__ float g_ffn [TOK * DFF];

// ----------------------------------------------------------------------------
// SGEMM: C[M,N] = A[M,K] @ W[K,N] + bias[N] (+ R[M,N]) (optional ReLU)
// BM=BN=128, BK=8, 256 threads, 8x8 per thread. All dims multiples of 128/8.
// ----------------------------------------------------------------------------
template<bool RELU, bool RES>
__global__ __launch_bounds__(256) void sgemm_kernel(
    const float* __restrict__ A, const float* __restrict__ W,
    const float* __restrict__ bias, const float* __restrict__ R,
    float* __restrict__ C, int M, int N, int K)
{
    __shared__ float As[8][128];
    __shared__ float Bs[8][128];

    const int tid = threadIdx.x;
    const int bm = blockIdx.y * 128;
    const int bn = blockIdx.x * 128;

    const int arow  = tid >> 1;          // 0..127
    const int acol4 = (tid & 1) * 4;     // 0 or 4
    const int brow  = tid >> 5;          // 0..7
    const int bcol4 = (tid & 31) * 4;    // 0..124

    const int tx = tid & 15;             // 0..15 -> col block
    const int ty = tid >> 4;             // 0..15 -> row block

    float acc[8][8];
#pragma unroll
    for (int i = 0; i < 8; i++)
#pragma unroll
        for (int j = 0; j < 8; j++) acc[i][j] = 0.f;

    const float* Aptr = A + (size_t)(bm + arow) * K + acol4;
    const float* Wptr = W + (size_t)brow * N + bn + bcol4;

    for (int k0 = 0; k0 < K; k0 += 8) {
        float4 av = *(const float4*)(Aptr + k0);
        As[acol4 + 0][arow] = av.x;
        As[acol4 + 1][arow] = av.y;
        As[acol4 + 2][arow] = av.z;
        As[acol4 + 3][arow] = av.w;
        float4 bv = *(const float4*)(Wptr + (size_t)k0 * N);
        *(float4*)(&Bs[brow][bcol4]) = bv;
        __syncthreads();

#pragma unroll
        for (int kk = 0; kk < 8; kk++) {
            float a[8], b[8];
            float4 a0 = *(const float4*)(&As[kk][ty * 8]);
            float4 a1 = *(const float4*)(&As[kk][ty * 8 + 4]);
            a[0]=a0.x; a[1]=a0.y; a[2]=a0.z; a[3]=a0.w;
            a[4]=a1.x; a[5]=a1.y; a[6]=a1.z; a[7]=a1.w;
            float4 b0 = *(const float4*)(&Bs[kk][tx * 8]);
            float4 b1 = *(const float4*)(&Bs[kk][tx * 8 + 4]);
            b[0]=b0.x; b[1]=b0.y; b[2]=b0.z; b[3]=b0.w;
            b[4]=b1.x; b[5]=b1.y; b[6]=b1.z; b[7]=b1.w;
#pragma unroll
            for (int i = 0; i < 8; i++)
#pragma unroll
                for (int j = 0; j < 8; j++)
                    acc[i][j] = fmaf(a[i], b[j], acc[i][j]);
        }
        __syncthreads();
    }

    // epilogue: vectorized float4 stores (two 4-col groups per row)
    const float4 bias0 = *(const float4*)(bias + bn + tx * 8);
    const float4 bias1 = *(const float4*)(bias + bn + tx * 8 + 4);
#pragma unroll
    for (int i = 0; i < 8; i++) {
        const int row = bm + ty * 8 + i;
        float* crow = C + (size_t)row * N + bn + tx * 8;
        float4 v0, v1;
        v0.x = acc[i][0] + bias0.x; v0.y = acc[i][1] + bias0.y;
        v0.z = acc[i][2] + bias0.z; v0.w = acc[i][3] + bias0.w;
        v1.x = acc[i][4] + bias1.x; v1.y = acc[i][5] + bias1.y;
        v1.z = acc[i][6] + bias1.z; v1.w = acc[i][7] + bias1.w;
        if (RES) {
            const float* rrow = R + (size_t)row * N + bn + tx * 8;
            float4 r0 = *(const float4*)(rrow);
            float4 r1 = *(const float4*)(rrow + 4);
            v0.x += r0.x; v0.y += r0.y; v0.z += r0.z; v0.w += r0.w;
            v1.x += r1.x; v1.y += r1.y; v1.z += r1.z; v1.w += r1.w;
        }
        if (RELU) {
            v0.x = fmaxf(v0.x, 0.f); v0.y = fmaxf(v0.y, 0.f);
            v0.z = fmaxf(v0.z, 0.f); v0.w = fmaxf(v0.w, 0.f);
            v1.x = fmaxf(v1.x, 0.f); v1.y = fmaxf(v1.y, 0.f);
            v1.z = fmaxf(v1.z, 0.f); v1.w = fmaxf(v1.w, 0.f);
        }
        *(float4*)(crow)     = v0;
        *(float4*)(crow + 4) = v1;
    }
}

// ----------------------------------------------------------------------------
// Streaming (flash-style) attention.
// Q,K,V viewed as [B][NHEADS][SEQ][HDIM] contiguous (the reference's reshape).
// Output written as O[b*SEQ + s][h*HDIM + d]  (folds the (0,2,1,3) transpose).
// 8 warps/block = 8 q rows; KV tiles of 64 staged in smem (K transposed).
// ----------------------------------------------------------------------------
template<bool CAUSAL>
__global__ __launch_bounds__(256) void attn_kernel(
    const float* __restrict__ Q, const float* __restrict__ K,
    const float* __restrict__ V, float* __restrict__ O)
{
    __shared__ float kT[HDIM][64];   // [d][j]
    __shared__ float vs[64][HDIM];   // [j][d]
    __shared__ float ps[8][64];      // probabilities per warp-row

    const int b = blockIdx.z;
    const int h = blockIdx.y;
    const int qbase = blockIdx.x * 8;
    const int warp = threadIdx.x >> 5;
    const int lane = threadIdx.x & 31;
    const int tid = threadIdx.x;

    const int qi = qbase + warp;                       // reshaped seq index
    const size_t head_off = ((size_t)(b * NHEADS + h)) * SEQ * HDIM;

    // load my q row into registers
    float q[HDIM];
    {
        const float4* qp = (const float4*)(Q + head_off + (size_t)qi * HDIM);
#pragma unroll
        for (int i = 0; i < HDIM / 4; i++) {
            float4 t = qp[i];
            q[4*i+0]=t.x; q[4*i+1]=t.y; q[4*i+2]=t.z; q[4*i+3]=t.w;
        }
    }

    float o0 = 0.f, o1 = 0.f;
    float m = -1e30f, lsum = 0.f;
    const float scale = 0.125f;   // 1/sqrt(64)

    const int ntiles = CAUSAL ? ((qbase + 7) / 64 + 1) : (SEQ / 64);

    for (int t = 0; t < ntiles; t++) {
        const int j0 = t * 64;
        // cooperative load: 64x64 K (transposed into kT) and V tiles
#pragma unroll
        for (int r = 0; r < 4; r++) {
            const int idx = tid + r * 256;      // 0..1023 float4 slots
            const int jr = idx >> 4;            // 0..63
            const int c4 = (idx & 15) * 4;      // 0..60
            const size_t g = head_off + (size_t)(j0 + jr) * HDIM + c4;
            float4 kvv = *(const float4*)(K + g);
            kT[c4 + 0][jr] = kvv.x;
            kT[c4 + 1][jr] = kvv.y;
            kT[c4 + 2][jr] = kvv.z;
            kT[c4 + 3][jr] = kvv.w;
            float4 vvv = *(const float4*)(V + g);
            *(float4*)(&vs[jr][c4]) = vvv;
        }
        __syncthreads();

        // scores for j = lane and j = lane+32
        float s0 = 0.f, s1 = 0.f;
#pragma unroll
        for (int d = 0; d < HDIM; d++) {
            s0 = fmaf(q[d], kT[d][lane], s0);
            s1 = fmaf(q[d], kT[d][lane + 32], s1);
        }
        s0 *= scale; s1 *= scale;
        if (CAUSAL) {
            if (j0 + lane > qi)      s0 = -1e30f;
            if (j0 + lane + 32 > qi) s1 = -1e30f;
        }

        // online softmax
        float mt = fmaxf(s0, s1);
#pragma unroll
        for (int off = 16; off > 0; off >>= 1)
            mt = fmaxf(mt, __shfl_xor_sync(0xffffffffu, mt, off));
        const float mnew = fmaxf(m, mt);
        const float p0 = __expf(s0 - mnew);
        const float p1 = __expf(s1 - mnew);
        const float corr = __expf(m - mnew);
        o0 *= corr; o1 *= corr;
        float psum = p0 + p1;
#pragma unroll
        for (int off = 16; off > 0; off >>= 1)
            psum += __shfl_xor_sync(0xffffffffu, psum, off);
        lsum = lsum * corr + psum;
        m = mnew;

        ps[warp][lane] = p0;
        ps[warp][lane + 32] = p1;
        __syncwarp();

        // O accumulation: lane owns d = lane, lane+32
#pragma unroll
        for (int j = 0; j < 64; j++) {
            const float pj = ps[warp][j];
            o0 = fmaf(pj, vs[j][lane], o0);
            o1 = fmaf(pj, vs[j][lane + 32], o1);
        }
        __syncthreads();
    }

    const float inv = 1.f / lsum;
    float* outp = O + (size_t)(b * SEQ + qi) * DMODEL + h * HDIM;
    outp[lane]      = o0 * inv;
    outp[lane + 32] = o1 * inv;
}

// ----------------------------------------------------------------------------
// LayerNorm: Y[row] = (X[row]-mu)*rstd*g + b ; one block per row of 1024.
// ----------------------------------------------------------------------------
__global__ __launch_bounds__(256) void ln_kernel(
    const float* __restrict__ X, const float* __restrict__ g,
    const float* __restrict__ bb, float* __restrict__ Y)
{
    __shared__ float red[16];
    const int row = blockIdx.x;
    const int tid = threadIdx.x;
    const float4 xv = *(const float4*)(X + (size_t)row * DMODEL + tid * 4);

    float s  = xv.x + xv.y + xv.z + xv.w;
    float sq = xv.x*xv.x + xv.y*xv.y + xv.z*xv.z + xv.w*xv.w;
#pragma unroll
    for (int off = 16; off > 0; off >>= 1) {
        s  += __shfl_xor_sync(0xffffffffu, s,  off);
        sq += __shfl_xor_sync(0xffffffffu, sq, off);
    }
    const int warp = tid >> 5, lane = tid & 31;
    if (lane == 0) { red[warp] = s; red[warp + 8] = sq; }
    __syncthreads();
    if (warp == 0) {
        float a = (lane < 8) ? red[lane] : 0.f;
        float c = (lane < 8) ? red[lane + 8] : 0.f;
#pragma unroll
        for (int off = 4; off > 0; off >>= 1) {
            a += __shfl_xor_sync(0xffffffffu, a, off);
            c += __shfl_xor_sync(0xffffffffu, c, off);
        }
        if (lane == 0) { red[0] = a; red[1] = c; }
    }
    __syncthreads();
    const float mu  = red[0] * (1.f / DMODEL);
    const float var = red[1] * (1.f / DMODEL) - mu * mu;
    const float rstd = rsqrtf(var + LN_EPS);

    const float4 gv = *(const float4*)(g  + tid * 4);
    const float4 bv = *(const float4*)(bb + tid * 4);
    float4 yv;
    yv.x = (xv.x - mu) * rstd * gv.x + bv.x;
    yv.y = (xv.y - mu) * rstd * gv.y + bv.y;
    yv.z = (xv.z - mu) * rstd * gv.z + bv.z;
    yv.w = (xv.w - mu) * rstd * gv.w + bv.w;
    *(float4*)(Y + (size_t)row * DMODEL + tid * 4) = yv;
}

// ----------------------------------------------------------------------------
// Launch
// ----------------------------------------------------------------------------
extern "C" void kernel_launch(void* const* d_in, const int* in_sizes, int n_in,
                              void* d_out, int out_size)
{
    const float* x    = (const float*)d_in[0];
    const float* enc  = (const float*)d_in[1];
    const float* s_wq = (const float*)d_in[2];  const float* s_bq = (const float*)d_in[3];
    const float* s_wk = (const float*)d_in[4];  const float* s_bk = (const float*)d_in[5];
    const float* s_wv = (const float*)d_in[6];  const float* s_bv = (const float*)d_in[7];
    const float* s_wo = (const float*)d_in[8];  const float* s_bo = (const float*)d_in[9];
    const float* c_wq = (const float*)d_in[10]; const float* c_bq = (const float*)d_in[11];
    const float* c_wk = (const float*)d_in[12]; const float* c_bk = (const float*)d_in[13];
    const float* c_wv = (const float*)d_in[14]; const float* c_bv = (const float*)d_in[15];
    const float* c_wo = (const float*)d_in[16]; const float* c_bo = (const float*)d_in[17];
    const float* f_w1 = (const float*)d_in[18]; const float* f_b1 = (const float*)d_in[19];
    const float* f_w2 = (const float*)d_in[20]; const float* f_b2 = (const float*)d_in[21];
    const float* ln1g = (const float*)d_in[22]; const float* ln1b = (const float*)d_in[23];
    const float* ln2g = (const float*)d_in[24]; const float* ln2b = (const float*)d_in[25];
    const float* ln3g = (const float*)d_in[26]; const float* ln3b = (const float*)d_in[27];
    float* out = (float*)d_out;

    float *q, *k, *v, *attn, *tmp, *y1, *y2, *ffn;
    cudaGetSymbolAddress((void**)&q,    g_q);
    cudaGetSymbolAddress((void**)&k,    g_k);
    cudaGetSymbolAddress((void**)&v,    g_v);
    cudaGetSymbolAddress((void**)&attn, g_attn);
    cudaGetSymbolAddress((void**)&tmp,  g_tmp);
    cudaGetSymbolAddress((void**)&y1,   g_y1);
    cudaGetSymbolAddress((void**)&y2,   g_y2);
    cudaGetSymbolAddress((void**)&ffn,  g_ffn);

    const dim3 blk(256);
    const dim3 g1024(DMODEL / 128, TOK / 128);   // N=1024 GEMMs
    const dim3 g4096(DFF / 128,    TOK / 128);   // N=4096 GEMM
    const dim3 gatt(SEQ / 8, NHEADS, BATCH);
    const dim3 gln(TOK);

    // ---- self attention ----
    sgemm_kernel<false,false><<<g1024, blk>>>(x, s_wq, s_bq, nullptr, q, TOK, DMODEL, DMODEL);
    sgemm_kernel<false,false><<<g1024, blk>>>(x, s_wk, s_bk, nullptr, k, TOK, DMODEL, DMODEL);
    sgemm_kernel<false,false><<<g1024, blk>>>(x, s_wv, s_bv, nullptr, v, TOK, DMODEL, DMODEL);
    attn_kernel<true><<<gatt, blk>>>(q, k, v, attn);
    sgemm_kernel<false,true><<<g1024, blk>>>(attn, s_wo, s_bo, x, tmp, TOK, DMODEL, DMODEL);
    ln_kernel<<<gln, blk>>>(tmp, ln1g, ln1b, y1);

    // ---- cross attention ----
    sgemm_kernel<false,false><<<g1024, blk>>>(y1,  c_wq, c_bq, nullptr, q, TOK, DMODEL, DMODEL);
    sgemm_kernel<false,false><<<g1024, blk>>>(enc, c_wk, c_bk, nullptr, k, TOK, DMODEL, DMODEL);
    sgemm_kernel<false,false><<<g1024, blk>>>(enc, c_wv, c_bv, nullptr, v, TOK, DMODEL, DMODEL);
    attn_kernel<false><<<gatt, blk>>>(q, k, v, attn);
    sgemm_kernel<false,true><<<g1024, blk>>>(attn, c_wo, c_bo, y1, tmp, TOK, DMODEL, DMODEL);
    ln_kernel<<<gln, blk>>>(tmp, ln2g, ln2b, y2);

    // ---- FFN ----
    sgemm_kernel<true,false><<<g4096, blk>>>(y2, f_w1, f_b1, nullptr, ffn, TOK, DFF, DMODEL);
    sgemm_kernel<false,true><<<g1024, blk>>>(ffn, f_w2, f_b2, y2, tmp, TOK, DMODEL, DFF);
    ln_kernel<<<gln, blk>>>(tmp, ln3g, ln3b, out);
}

// round 5
// speedup vs baseline: 1.2828x; 1.2828x over previous
#include <cuda_runtime.h>
#include <cuda_bf16.h>
#include <math.h>
#include <stdint.h>

// ----------------------------------------------------------------------------
// Problem constants
// ----------------------------------------------------------------------------
#define BATCH   2
#define SEQ     2048
#define TOK     (BATCH * SEQ)        // 4096 rows
#define DMODEL  1024
#define DFF     4096
#define NHEADS  16
#define HDIM    64                   // head dim
#define LN_EPS  1e-5f

// ----------------------------------------------------------------------------
// Scratch buffers (static device allocations; no cudaMalloc allowed)
// ----------------------------------------------------------------------------
__device__ float g_q   [TOK * DMODEL];
__device__ float g_k   [TOK * DMODEL];
__device__ float g_v   [TOK * DMODEL];
__device__ float g_attn[TOK * DMODEL];
__device__ float g_tmp [TOK * DMODEL];
__device__ float g_y1  [TOK * DMODEL];
__device__ float g_y2  [TOK * DMODEL];
__device__ float g_ffn [TOK * DFF];

// ----------------------------------------------------------------------------
// tf32 tensor-core GEMM
//   C[M,N] = A[M,K] @ W[K,N] + bias[N] (+ R) (optional ReLU)
//   BM=BN=128, BK=16, 256 threads (8 warps as 2x4), warp tile 64x32.
//   mma.sync.m16n8k8 tf32, fp32 accumulate. Inputs rounded once (cvt.rna)
//   at smem staging. blockIdx.z selects among up to 3 fused problems
//   (shared tile shapes) so QKV runs as a single launch.
// ----------------------------------------------------------------------------
struct GemmArgs {
    const float* A[3];
    const float* W[3];
    const float* bias[3];
    const float* R[3];
    float*       C[3];
    int N, K;
};

__device__ __forceinline__ float f2tf32(float x) {
    uint32_t r;
    asm("cvt.rna.tf32.f32 %0, %1;" : "=r"(r) : "f"(x));
    return __uint_as_float(r);
}

#define AS_STRIDE 20    // floats per A smem row (16 used + 4 pad) -> conflict-free frags
#define BS_STRIDE 136   // floats per B smem row (128 used + 8 pad) -> conflict-free frags

template<bool RELU, bool RES>
__global__ __launch_bounds__(256, 2) void gemm_tf32(GemmArgs args)
{
    const int zi = blockIdx.z;
    const float* __restrict__ A    = args.A[zi];
    const float* __restrict__ W    = args.W[zi];
    const float* __restrict__ bias = args.bias[zi];
    const float* __restrict__ Rp   = args.R[zi];
    float*       __restrict__ C    = args.C[zi];
    const int N = args.N, K = args.K;

    __shared__ float As[2][128 * AS_STRIDE];
    __shared__ float Bs[2][16 * BS_STRIDE];

    const int tid  = threadIdx.x;
    const int lane = tid & 31;
    const int warp = tid >> 5;
    const int g    = lane >> 2;          // 0..7 (group)
    const int tg   = lane & 3;           // 0..3 (thread in group)
    const int wm   = (warp >> 2) * 64;   // warp row offset: 0 / 64
    const int wn   = (warp & 3) * 32;    // warp col offset: 0/32/64/96
    const int bm   = blockIdx.y * 128;
    const int bn   = blockIdx.x * 128;

    // global-load mapping
    const int a_row = tid >> 2;          // 0..63 (and +64)
    const int a_c4  = (tid & 3) * 4;     // 0..12
    const int b_row = tid >> 5;          // 0..7  (and +8)
    const int b_c4  = (tid & 31) * 4;    // 0..124

    const float* Ag0 = A + (size_t)(bm + a_row)      * K + a_c4;
    const float* Ag1 = A + (size_t)(bm + a_row + 64) * K + a_c4;
    const float* Wg0 = W + (size_t)(b_row)     * N + bn + b_c4;
    const float* Wg1 = W + (size_t)(b_row + 8) * N + bn + b_c4;

    float acc[4][4][4];
#pragma unroll
    for (int i = 0; i < 4; i++)
#pragma unroll
        for (int j = 0; j < 4; j++)
#pragma unroll
            for (int r = 0; r < 4; r++) acc[i][j][r] = 0.f;

    float4 ra0, ra1, rb0, rb1;

#define LOADG(t) do {                                             \
        const size_t ka = (size_t)(t) * 16;                       \
        const size_t kb = (size_t)(t) * 16 * (size_t)N;           \
        ra0 = *(const float4*)(Ag0 + ka);                         \
        ra1 = *(const float4*)(Ag1 + ka);                         \
        rb0 = *(const float4*)(Wg0 + kb);                         \
        rb1 = *(const float4*)(Wg1 + kb);                         \
    } while (0)

#define STORES(buf) do {                                          \
        float* as_ = As[buf];                                     \
        float* bs_ = Bs[buf];                                     \
        float4 t0;                                                \
        t0.x = f2tf32(ra0.x); t0.y = f2tf32(ra0.y);               \
        t0.z = f2tf32(ra0.z); t0.w = f2tf32(ra0.w);               \
        *(float4*)(as_ + a_row * AS_STRIDE + a_c4) = t0;          \
        t0.x = f2tf32(ra1.x); t0.y = f2tf32(ra1.y);               \
        t0.z = f2tf32(ra1.z); t0.w = f2tf32(ra1.w);               \
        *(float4*)(as_ + (a_row + 64) * AS_STRIDE + a_c4) = t0;   \
        t0.x = f2tf32(rb0.x); t0.y = f2tf32(rb0.y);               \
        t0.z = f2tf32(rb0.z); t0.w = f2tf32(rb0.w);               \
        *(float4*)(bs_ + b_row * BS_STRIDE + b_c4) = t0;          \
        t0.x = f2tf32(rb1.x); t0.y = f2tf32(rb1.y);               \
        t0.z = f2tf32(rb1.z); t0.w = f2tf32(rb1.w);               \
        *(float4*)(bs_ + (b_row + 8) * BS_STRIDE + b_c4) = t0;    \
    } while (0)

    const int NT = K >> 4;

    LOADG(0);
    STORES(0);
    __syncthreads();

    for (int t = 0; t < NT; t++) {
        const int cur = t & 1;
        if (t + 1 < NT) LOADG(t + 1);

        const float* as_ = As[cur];
        const float* bs_ = Bs[cur];
#pragma unroll
        for (int kk = 0; kk < 16; kk += 8) {
            unsigned af[4][4], bf[4][2];
#pragma unroll
            for (int mt = 0; mt < 4; mt++) {
                const float* ap = as_ + (wm + mt * 16 + g) * AS_STRIDE + kk + tg;
                af[mt][0] = __float_as_uint(ap[0]);
                af[mt][1] = __float_as_uint(ap[8 * AS_STRIDE]);
                af[mt][2] = __float_as_uint(ap[4]);
                af[mt][3] = __float_as_uint(ap[8 * AS_STRIDE + 4]);
            }
#pragma unroll
            for (int nt = 0; nt < 4; nt++) {
                const float* bp = bs_ + (kk + tg) * BS_STRIDE + wn + nt * 8 + g;
                bf[nt][0] = __float_as_uint(bp[0]);
                bf[nt][1] = __float_as_uint(bp[4 * BS_STRIDE]);
            }
#pragma unroll
            for (int mt = 0; mt < 4; mt++)
#pragma unroll
                for (int nt = 0; nt < 4; nt++)
                    asm volatile(
                        "mma.sync.aligned.m16n8k8.row.col.f32.tf32.tf32.f32 "
                        "{%0,%1,%2,%3}, {%4,%5,%6,%7}, {%8,%9}, {%0,%1,%2,%3};"
                        : "+f"(acc[mt][nt][0]), "+f"(acc[mt][nt][1]),
                          "+f"(acc[mt][nt][2]), "+f"(acc[mt][nt][3])
                        : "r"(af[mt][0]), "r"(af[mt][1]),
                          "r"(af[mt][2]), "r"(af[mt][3]),
                          "r"(bf[nt][0]), "r"(bf[nt][1]));
        }

        if (t + 1 < NT) STORES((t + 1) & 1);
        __syncthreads();
    }

    // epilogue: C-fragment rows = g, g+8 ; cols = 2*tg, 2*tg+1
#pragma unroll
    for (int mt = 0; mt < 4; mt++) {
        const int row0 = bm + wm + mt * 16 + g;
#pragma unroll
        for (int nt = 0; nt < 4; nt++) {
            const int col = bn + wn + nt * 8 + tg * 2;
            const float bv0 = bias[col], bv1 = bias[col + 1];
            float2 v0, v1;
            v0.x = acc[mt][nt][0] + bv0; v0.y = acc[mt][nt][1] + bv1;
            v1.x = acc[mt][nt][2] + bv0; v1.y = acc[mt][nt][3] + bv1;
            if (RES) {
                float2 r0 = *(const float2*)(Rp + (size_t)row0 * N + col);
                float2 r1 = *(const float2*)(Rp + (size_t)(row0 + 8) * N + col);
                v0.x += r0.x; v0.y += r0.y;
                v1.x += r1.x; v1.y += r1.y;
            }
            if (RELU) {
                v0.x = fmaxf(v0.x, 0.f); v0.y = fmaxf(v0.y, 0.f);
                v1.x = fmaxf(v1.x, 0.f); v1.y = fmaxf(v1.y, 0.f);
            }
            *(float2*)(C + (size_t)row0 * N + col)       = v0;
            *(float2*)(C + (size_t)(row0 + 8) * N + col) = v1;
        }
    }
#undef LOADG
#undef STORES
}

// ----------------------------------------------------------------------------
// Streaming (flash-style) attention.
// Q,K,V viewed as [B][NHEADS][SEQ][HDIM] contiguous (the reference's reshape).
// Output written as O[b*SEQ + s][h*HDIM + d]  (folds the (0,2,1,3) transpose).
// 8 warps/block = 8 q rows; KV tiles of 64 staged in smem (K transposed).
// ----------------------------------------------------------------------------
template<bool CAUSAL>
__global__ __launch_bounds__(256) void attn_kernel(
    const float* __restrict__ Q, const float* __restrict__ K,
    const float* __restrict__ V, float* __restrict__ O)
{
    __shared__ float kT[HDIM][64];   // [d][j]
    __shared__ float vs[64][HDIM];   // [j][d]
    __shared__ float ps[8][64];      // probabilities per warp-row

    const int b = blockIdx.z;
    const int h = blockIdx.y;
    const int qbase = blockIdx.x * 8;
    const int warp = threadIdx.x >> 5;
    const int lane = threadIdx.x & 31;
    const int tid = threadIdx.x;

    const int qi = qbase + warp;                       // reshaped seq index
    const size_t head_off = ((size_t)(b * NHEADS + h)) * SEQ * HDIM;

    // load my q row into registers
    float q[HDIM];
    {
        const float4* qp = (const float4*)(Q + head_off + (size_t)qi * HDIM);
#pragma unroll
        for (int i = 0; i < HDIM / 4; i++) {
            float4 t = qp[i];
            q[4*i+0]=t.x; q[4*i+1]=t.y; q[4*i+2]=t.z; q[4*i+3]=t.w;
        }
    }

    float o0 = 0.f, o1 = 0.f;
    float m = -1e30f, lsum = 0.f;
    const float scale = 0.125f;   // 1/sqrt(64)

    const int ntiles = CAUSAL ? ((qbase + 7) / 64 + 1) : (SEQ / 64);

    for (int t = 0; t < ntiles; t++) {
        const int j0 = t * 64;
#pragma unroll
        for (int r = 0; r < 4; r++) {
            const int idx = tid + r * 256;      // 0..1023 float4 slots
            const int jr = idx >> 4;            // 0..63
            const int c4 = (idx & 15) * 4;      // 0..60
            const size_t gaddr = head_off + (size_t)(j0 + jr) * HDIM + c4;
            float4 kvv = *(const float4*)(K + gaddr);
            kT[c4 + 0][jr] = kvv.x;
            kT[c4 + 1][jr] = kvv.y;
            kT[c4 + 2][jr] = kvv.z;
            kT[c4 + 3][jr] = kvv.w;
            float4 vvv = *(const float4*)(V + gaddr);
            *(float4*)(&vs[jr][c4]) = vvv;
        }
        __syncthreads();

        float s0 = 0.f, s1 = 0.f;
#pragma unroll
        for (int d = 0; d < HDIM; d++) {
            s0 = fmaf(q[d], kT[d][lane], s0);
            s1 = fmaf(q[d], kT[d][lane + 32], s1);
        }
        s0 *= scale; s1 *= scale;
        if (CAUSAL) {
            if (j0 + lane > qi)      s0 = -1e30f;
            if (j0 + lane + 32 > qi) s1 = -1e30f;
        }

        float mt = fmaxf(s0, s1);
#pragma unroll
        for (int off = 16; off > 0; off >>= 1)
            mt = fmaxf(mt, __shfl_xor_sync(0xffffffffu, mt, off));
        const float mnew = fmaxf(m, mt);
        const float p0 = __expf(s0 - mnew);
        const float p1 = __expf(s1 - mnew);
        const float corr = __expf(m - mnew);
        o0 *= corr; o1 *= corr;
        float psum = p0 + p1;
#pragma unroll
        for (int off = 16; off > 0; off >>= 1)
            psum += __shfl_xor_sync(0xffffffffu, psum, off);
        lsum = lsum * corr + psum;
        m = mnew;

        ps[warp][lane] = p0;
        ps[warp][lane + 32] = p1;
        __syncwarp();

#pragma unroll
        for (int j = 0; j < 64; j++) {
            const float pj = ps[warp][j];
            o0 = fmaf(pj, vs[j][lane], o0);
            o1 = fmaf(pj, vs[j][lane + 32], o1);
        }
        __syncthreads();
    }

    const float inv = 1.f / lsum;
    float* outp = O + (size_t)(b * SEQ + qi) * DMODEL + h * HDIM;
    outp[lane]      = o0 * inv;
    outp[lane + 32] = o1 * inv;
}

// ----------------------------------------------------------------------------
// LayerNorm: Y[row] = (X[row]-mu)*rstd*g + b ; one block per row of 1024.
// ----------------------------------------------------------------------------
__global__ __launch_bounds__(256) void ln_kernel(
    const float* __restrict__ X, const float* __restrict__ g,
    const float* __restrict__ bb, float* __restrict__ Y)
{
    __shared__ float red[16];
    const int row = blockIdx.x;
    const int tid = threadIdx.x;
    const float4 xv = *(const float4*)(X + (size_t)row * DMODEL + tid * 4);

    float s  = xv.x + xv.y + xv.z + xv.w;
    float sq = xv.x*xv.x + xv.y*xv.y + xv.z*xv.z + xv.w*xv.w;
#pragma unroll
    for (int off = 16; off > 0; off >>= 1) {
        s  += __shfl_xor_sync(0xffffffffu, s,  off);
        sq += __shfl_xor_sync(0xffffffffu, sq, off);
    }
    const int warp = tid >> 5, lane = tid & 31;
    if (lane == 0) { red[warp] = s; red[warp + 8] = sq; }
    __syncthreads();
    if (warp == 0) {
        float a = (lane < 8) ? red[lane] : 0.f;
        float c = (lane < 8) ? red[lane + 8] : 0.f;
#pragma unroll
        for (int off = 4; off > 0; off >>= 1) {
            a += __shfl_xor_sync(0xffffffffu, a, off);
            c += __shfl_xor_sync(0xffffffffu, c, off);
        }
        if (lane == 0) { red[0] = a; red[1] = c; }
    }
    __syncthreads();
    const float mu  = red[0] * (1.f / DMODEL);
    const float var = red[1] * (1.f / DMODEL) - mu * mu;
    const float rstd = rsqrtf(var + LN_EPS);

    const float4 gv = *(const float4*)(g  + tid * 4);
    const float4 bv = *(const float4*)(bb + tid * 4);
    float4 yv;
    yv.x = (xv.x - mu) * rstd * gv.x + bv.x;
    yv.y = (xv.y - mu) * rstd * gv.y + bv.y;
    yv.z = (xv.z - mu) * rstd * gv.z + bv.z;
    yv.w = (xv.w - mu) * rstd * gv.w + bv.w;
    *(float4*)(Y + (size_t)row * DMODEL + tid * 4) = yv;
}

// ----------------------------------------------------------------------------
// Launch
// ----------------------------------------------------------------------------
extern "C" void kernel_launch(void* const* d_in, const int* in_sizes, int n_in,
                              void* d_out, int out_size)
{
    const float* x    = (const float*)d_in[0];
    const float* enc  = (const float*)d_in[1];
    const float* s_wq = (const float*)d_in[2];  const float* s_bq = (const float*)d_in[3];
    const float* s_wk = (const float*)d_in[4];  const float* s_bk = (const float*)d_in[5];
    const float* s_wv = (const float*)d_in[6];  const float* s_bv = (const float*)d_in[7];
    const float* s_wo = (const float*)d_in[8];  const float* s_bo = (const float*)d_in[9];
    const float* c_wq = (const float*)d_in[10]; const float* c_bq = (const float*)d_in[11];
    const float* c_wk = (const float*)d_in[12]; const float* c_bk = (const float*)d_in[13];
    const float* c_wv = (const float*)d_in[14]; const float* c_bv = (const float*)d_in[15];
    const float* c_wo = (const float*)d_in[16]; const float* c_bo = (const float*)d_in[17];
    const float* f_w1 = (const float*)d_in[18]; const float* f_b1 = (const float*)d_in[19];
    const float* f_w2 = (const float*)d_in[20]; const float* f_b2 = (const float*)d_in[21];
    const float* ln1g = (const float*)d_in[22]; const float* ln1b = (const float*)d_in[23];
    const float* ln2g = (const float*)d_in[24]; const float* ln2b = (const float*)d_in[25];
    const float* ln3g = (const float*)d_in[26]; const float* ln3b = (const float*)d_in[27];
    float* out = (float*)d_out;

    float *q, *k, *v, *attn, *tmp, *y1, *y2, *ffn;
    cudaGetSymbolAddress((void**)&q,    g_q);
    cudaGetSymbolAddress((void**)&k,    g_k);
    cudaGetSymbolAddress((void**)&v,    g_v);
    cudaGetSymbolAddress((void**)&attn, g_attn);
    cudaGetSymbolAddress((void**)&tmp,  g_tmp);
    cudaGetSymbolAddress((void**)&y1,   g_y1);
    cudaGetSymbolAddress((void**)&y2,   g_y2);
    cudaGetSymbolAddress((void**)&ffn,  g_ffn);

    const dim3 blk(256);
    const dim3 gatt(SEQ / 8, NHEADS, BATCH);
    const dim3 gln(TOK);

    GemmArgs ga;

    // ---- self attention: fused QKV projection (z=3) ----
    ga = GemmArgs{};
    ga.A[0] = x;    ga.A[1] = x;    ga.A[2] = x;
    ga.W[0] = s_wq; ga.W[1] = s_wk; ga.W[2] = s_wv;
    ga.bias[0] = s_bq; ga.bias[1] = s_bk; ga.bias[2] = s_bv;
    ga.R[0] = x; ga.R[1] = x; ga.R[2] = x;
    ga.C[0] = q; ga.C[1] = k; ga.C[2] = v;
    ga.N = DMODEL; ga.K = DMODEL;
    gemm_tf32<false,false><<<dim3(DMODEL/128, TOK/128, 3), blk>>>(ga);

    attn_kernel<true><<<gatt, blk>>>(q, k, v, attn);

    ga.A[0] = attn; ga.W[0] = s_wo; ga.bias[0] = s_bo; ga.R[0] = x; ga.C[0] = tmp;
    gemm_tf32<false,true><<<dim3(DMODEL/128, TOK/128, 1), blk>>>(ga);
    ln_kernel<<<gln, blk>>>(tmp, ln1g, ln1b, y1);

    // ---- cross attention: fused Q(y1) + K,V(enc) projection (z=3) ----
    ga.A[0] = y1;   ga.A[1] = enc;  ga.A[2] = enc;
    ga.W[0] = c_wq; ga.W[1] = c_wk; ga.W[2] = c_wv;
    ga.bias[0] = c_bq; ga.bias[1] = c_bk; ga.bias[2] = c_bv;
    ga.R[0] = x; ga.R[1] = x; ga.R[2] = x;
    ga.C[0] = q; ga.C[1] = k; ga.C[2] = v;
    gemm_tf32<false,false><<<dim3(DMODEL/128, TOK/128, 3), blk>>>(ga);

    attn_kernel<false><<<gatt, blk>>>(q, k, v, attn);

    ga.A[0] = attn; ga.W[0] = c_wo; ga.bias[0] = c_bo; ga.R[0] = y1; ga.C[0] = tmp;
    gemm_tf32<false,true><<<dim3(DMODEL/128, TOK/128, 1), blk>>>(ga);
    ln_kernel<<<gln, blk>>>(tmp, ln2g, ln2b, y2);

    // ---- FFN ----
    ga.A[0] = y2; ga.W[0] = f_w1; ga.bias[0] = f_b1; ga.R[0] = x; ga.C[0] = ffn;
    ga.N = DFF; ga.K = DMODEL;
    gemm_tf32<true,false><<<dim3(DFF/128, TOK/128, 1), blk>>>(ga);

    ga.A[0] = ffn; ga.W[0] = f_w2; ga.bias[0] = f_b2; ga.R[0] = y2; ga.C[0] = tmp;
    ga.N = DMODEL; ga.K = DFF;
    gemm_tf32<false,true><<<dim3(DMODEL/128, TOK/128, 1), blk>>>(ga);
    ln_kernel<<<gln, blk>>>(tmp, ln3g, ln3b, out);
}

// round 6
// speedup vs baseline: 5.7211x; 4.4600x over previous
#include <cuda_runtime.h>
#include <cuda_bf16.h>
#include <math.h>
#include <stdint.h>

// ----------------------------------------------------------------------------
// Problem constants
// ----------------------------------------------------------------------------
#define BATCH   2
#define SEQ     2048
#define TOK     (BATCH * SEQ)        // 4096 rows
#define DMODEL  1024
#define DFF     4096
#define NHEADS  16
#define HDIM    64                   // head dim
#define LN_EPS  1e-5f

// ----------------------------------------------------------------------------
// Scratch buffers (static device allocations; no cudaMalloc allowed)
// ----------------------------------------------------------------------------
__device__ float g_q   [TOK * DMODEL];
__device__ float g_k   [TOK * DMODEL];
__device__ float g_v   [TOK * DMODEL];
__device__ float g_attn[TOK * DMODEL];
__device__ float g_tmp [TOK * DMODEL];
__device__ float g_y1  [TOK * DMODEL];
__device__ float g_y2  [TOK * DMODEL];
__device__ float g_ffn [TOK * DFF];

__device__ __forceinline__ float f2tf32(float x) {
    uint32_t r;
    asm("cvt.rna.tf32.f32 %0, %1;" : "=r"(r) : "f"(x));
    return __uint_as_float(r);
}

#define MMA_TF32(acc, a, b0v, b1v)                                         \
    asm volatile(                                                          \
        "mma.sync.aligned.m16n8k8.row.col.f32.tf32.tf32.f32 "              \
        "{%0,%1,%2,%3}, {%4,%5,%6,%7}, {%8,%9}, {%0,%1,%2,%3};"            \
        : "+f"((acc)[0]), "+f"((acc)[1]), "+f"((acc)[2]), "+f"((acc)[3])   \
        : "r"((a)[0]), "r"((a)[1]), "r"((a)[2]), "r"((a)[3]),              \
          "r"(b0v), "r"(b1v))

// ----------------------------------------------------------------------------
// tf32 tensor-core GEMM (unchanged from R5 pass)
// ----------------------------------------------------------------------------
struct GemmArgs {
    const float* A[3];
    const float* W[3];
    const float* bias[3];
    const float* R[3];
    float*       C[3];
    int N, K;
};

#define AS_STRIDE 20
#define BS_STRIDE 136

template<bool RELU, bool RES>
__global__ __launch_bounds__(256, 2) void gemm_tf32(GemmArgs args)
{
    const int zi = blockIdx.z;
    const float* __restrict__ A    = args.A[zi];
    const float* __restrict__ W    = args.W[zi];
    const float* __restrict__ bias = args.bias[zi];
    const float* __restrict__ Rp   = args.R[zi];
    float*       __restrict__ C    = args.C[zi];
    const int N = args.N, K = args.K;

    __shared__ float As[2][128 * AS_STRIDE];
    __shared__ float Bs[2][16 * BS_STRIDE];

    const int tid  = threadIdx.x;
    const int lane = tid & 31;
    const int warp = tid >> 5;
    const int g    = lane >> 2;
    const int tg   = lane & 3;
    const int wm   = (warp >> 2) * 64;
    const int wn   = (warp & 3) * 32;
    const int bm   = blockIdx.y * 128;
    const int bn   = blockIdx.x * 128;

    const int a_row = tid >> 2;
    const int a_c4  = (tid & 3) * 4;
    const int b_row = tid >> 5;
    const int b_c4  = (tid & 31) * 4;

    const float* Ag0 = A + (size_t)(bm + a_row)      * K + a_c4;
    const float* Ag1 = A + (size_t)(bm + a_row + 64) * K + a_c4;
    const float* Wg0 = W + (size_t)(b_row)     * N + bn + b_c4;
    const float* Wg1 = W + (size_t)(b_row + 8) * N + bn + b_c4;

    float acc[4][4][4];
#pragma unroll
    for (int i = 0; i < 4; i++)
#pragma unroll
        for (int j = 0; j < 4; j++)
#pragma unroll
            for (int r = 0; r < 4; r++) acc[i][j][r] = 0.f;

    float4 ra0, ra1, rb0, rb1;

#define LOADG(t) do {                                             \
        const size_t ka = (size_t)(t) * 16;                       \
        const size_t kb = (size_t)(t) * 16 * (size_t)N;           \
        ra0 = *(const float4*)(Ag0 + ka);                         \
        ra1 = *(const float4*)(Ag1 + ka);                         \
        rb0 = *(const float4*)(Wg0 + kb);                         \
        rb1 = *(const float4*)(Wg1 + kb);                         \
    } while (0)

#define STORES(buf) do {                                          \
        float* as_ = As[buf];                                     \
        float* bs_ = Bs[buf];                                     \
        float4 t0;                                                \
        t0.x = f2tf32(ra0.x); t0.y = f2tf32(ra0.y);               \
        t0.z = f2tf32(ra0.z); t0.w = f2tf32(ra0.w);               \
        *(float4*)(as_ + a_row * AS_STRIDE + a_c4) = t0;          \
        t0.x = f2tf32(ra1.x); t0.y = f2tf32(ra1.y);               \
        t0.z = f2tf32(ra1.z); t0.w = f2tf32(ra1.w);               \
        *(float4*)(as_ + (a_row + 64) * AS_STRIDE + a_c4) = t0;   \
        t0.x = f2tf32(rb0.x); t0.y = f2tf32(rb0.y);               \
        t0.z = f2tf32(rb0.z); t0.w = f2tf32(rb0.w);               \
        *(float4*)(bs_ + b_row * BS_STRIDE + b_c4) = t0;          \
        t0.x = f2tf32(rb1.x); t0.y = f2tf32(rb1.y);               \
        t0.z = f2tf32(rb1.z); t0.w = f2tf32(rb1.w);               \
        *(float4*)(bs_ + (b_row + 8) * BS_STRIDE + b_c4) = t0;    \
    } while (0)

    const int NT = K >> 4;

    LOADG(0);
    STORES(0);
    __syncthreads();

    for (int t = 0; t < NT; t++) {
        const int cur = t & 1;
        if (t + 1 < NT) LOADG(t + 1);

        const float* as_ = As[cur];
        const float* bs_ = Bs[cur];
#pragma unroll
        for (int kk = 0; kk < 16; kk += 8) {
            unsigned af[4][4], bf[4][2];
#pragma unroll
            for (int mt = 0; mt < 4; mt++) {
                const float* ap = as_ + (wm + mt * 16 + g) * AS_STRIDE + kk + tg;
                af[mt][0] = __float_as_uint(ap[0]);
                af[mt][1] = __float_as_uint(ap[8 * AS_STRIDE]);
                af[mt][2] = __float_as_uint(ap[4]);
                af[mt][3] = __float_as_uint(ap[8 * AS_STRIDE + 4]);
            }
#pragma unroll
            for (int nt = 0; nt < 4; nt++) {
                const float* bp = bs_ + (kk + tg) * BS_STRIDE + wn + nt * 8 + g;
                bf[nt][0] = __float_as_uint(bp[0]);
                bf[nt][1] = __float_as_uint(bp[4 * BS_STRIDE]);
            }
#pragma unroll
            for (int mt = 0; mt < 4; mt++)
#pragma unroll
                for (int nt = 0; nt < 4; nt++)
                    MMA_TF32(acc[mt][nt], af[mt], bf[nt][0], bf[nt][1]);
        }

        if (t + 1 < NT) STORES((t + 1) & 1);
        __syncthreads();
    }

#pragma unroll
    for (int mt = 0; mt < 4; mt++) {
        const int row0 = bm + wm + mt * 16 + g;
#pragma unroll
        for (int nt = 0; nt < 4; nt++) {
            const int col = bn + wn + nt * 8 + tg * 2;
            const float bv0 = bias[col], bv1 = bias[col + 1];
            float2 v0, v1;
            v0.x = acc[mt][nt][0] + bv0; v0.y = acc[mt][nt][1] + bv1;
            v1.x = acc[mt][nt][2] + bv0; v1.y = acc[mt][nt][3] + bv1;
            if (RES) {
                float2 r0 = *(const float2*)(Rp + (size_t)row0 * N + col);
                float2 r1 = *(const float2*)(Rp + (size_t)(row0 + 8) * N + col);
                v0.x += r0.x; v0.y += r0.y;
                v1.x += r1.x; v1.y += r1.y;
            }
            if (RELU) {
                v0.x = fmaxf(v0.x, 0.f); v0.y = fmaxf(v0.y, 0.f);
                v1.x = fmaxf(v1.x, 0.f); v1.y = fmaxf(v1.y, 0.f);
            }
            *(float2*)(C + (size_t)row0 * N + col)       = v0;
            *(float2*)(C + (size_t)(row0 + 8) * N + col) = v1;
        }
    }
#undef LOADG
#undef STORES
}

// ----------------------------------------------------------------------------
// Tensor-core flash attention (tf32 mma).
// Q,K,V viewed as [B][NHEADS][SEQ][HDIM] contiguous (reference reshape).
// CTA: 128 threads (4 warps), Q-tile 64 rows (16/warp), KV tiles of 64.
// S = Q@K^T and O += P@V via mma.sync.m16n8k8.tf32.
// Output written O[b*SEQ+s][h*64+d] (folds the (0,2,1,3) transpose).
// ----------------------------------------------------------------------------
#define ASTR 72   // smem row stride (floats): 64 + 8 pad
#define ATT_SMEM (256 * ASTR * 4)   // sQ(64) + sK(64) + sV(64) + sP(64) rows

template<bool CAUSAL>
__global__ __launch_bounds__(128) void attn_tc(
    const float* __restrict__ Q, const float* __restrict__ K,
    const float* __restrict__ V, float* __restrict__ O)
{
    extern __shared__ float sm[];
    float* sQ = sm;                 // [64][ASTR]
    float* sK = sm + 64 * ASTR;     // [64][ASTR]  (natural [key][d])
    float* sV = sm + 128 * ASTR;    // [64][ASTR]  (natural [key][d])
    float* sP = sm + 192 * ASTR;    // [4 warps][16][ASTR]

    const int b  = blockIdx.z;
    const int h  = blockIdx.y;
    const int q0 = blockIdx.x * 64;
    const int tid  = threadIdx.x;
    const int lane = tid & 31;
    const int w    = tid >> 5;
    const int g    = lane >> 2;
    const int tg   = lane & 3;
    const size_t hoff = ((size_t)(b * NHEADS + h)) * SEQ * HDIM;

    // ---- stage Q (scale folded; 0.125 = 2^-3 is exact in tf32) ----
#pragma unroll
    for (int i = 0; i < 8; i++) {
        const int idx = tid + i * 128;
        const int row = idx >> 4;
        const int c4  = (idx & 15) << 2;
        float4 t = *(const float4*)(Q + hoff + (size_t)(q0 + row) * HDIM + c4);
        float4 o;
        o.x = f2tf32(t.x * 0.125f); o.y = f2tf32(t.y * 0.125f);
        o.z = f2tf32(t.z * 0.125f); o.w = f2tf32(t.w * 0.125f);
        *(float4*)(sQ + row * ASTR + c4) = o;
    }
    __syncthreads();

    // ---- Q fragments: register resident for whole kernel ----
    unsigned aQ[8][4];
    {
        const float* qb = sQ + (w * 16 + g) * ASTR;
#pragma unroll
        for (int kk = 0; kk < 8; kk++) {
            aQ[kk][0] = __float_as_uint(qb[kk * 8 + tg]);
            aQ[kk][1] = __float_as_uint(qb[8 * ASTR + kk * 8 + tg]);
            aQ[kk][2] = __float_as_uint(qb[kk * 8 + tg + 4]);
            aQ[kk][3] = __float_as_uint(qb[8 * ASTR + kk * 8 + tg + 4]);
        }
    }

    float cO[8][4];
#pragma unroll
    for (int nt = 0; nt < 8; nt++)
#pragma unroll
        for (int r = 0; r < 4; r++) cO[nt][r] = 0.f;
    float mrow[2] = { -1e30f, -1e30f };
    float lrow[2] = { 0.f, 0.f };

    const int ntiles = CAUSAL ? (q0 / 64 + 1) : (SEQ / 64);

    for (int t = 0; t < ntiles; t++) {
        const int j0 = t * 64;
        __syncthreads();   // previous tile's smem reads done before restage
#pragma unroll
        for (int i = 0; i < 8; i++) {
            const int idx = tid + i * 128;
            const int row = idx >> 4;
            const int c4  = (idx & 15) << 2;
            const size_t gaddr = hoff + (size_t)(j0 + row) * HDIM + c4;
            float4 kt = *(const float4*)(K + gaddr);
            float4 ko;
            ko.x = f2tf32(kt.x); ko.y = f2tf32(kt.y);
            ko.z = f2tf32(kt.z); ko.w = f2tf32(kt.w);
            *(float4*)(sK + row * ASTR + c4) = ko;
            float4 vt = *(const float4*)(V + gaddr);
            float4 vo;
            vo.x = f2tf32(vt.x); vo.y = f2tf32(vt.y);
            vo.z = f2tf32(vt.z); vo.w = f2tf32(vt.w);
            *(float4*)(sV + row * ASTR + c4) = vo;
        }
        __syncthreads();

        // ---- S = Q @ K^T : B frag = K^T[d][key] read from sK[key][d] ----
        float cS[8][4];
#pragma unroll
        for (int nt = 0; nt < 8; nt++)
#pragma unroll
            for (int r = 0; r < 4; r++) cS[nt][r] = 0.f;

#pragma unroll
        for (int kk = 0; kk < 8; kk++)
#pragma unroll
            for (int nt = 0; nt < 8; nt++) {
                const float* kp = sK + (nt * 8 + g) * ASTR + kk * 8 + tg;
                unsigned b0 = __float_as_uint(kp[0]);
                unsigned b1 = __float_as_uint(kp[4]);
                MMA_TF32(cS[nt], aQ[kk], b0, b1);
            }

        // ---- causal mask (only diagonal tile needs it) ----
        if (CAUSAL && t == ntiles - 1) {
            const int rbase = q0 + w * 16 + g;
#pragma unroll
            for (int nt = 0; nt < 8; nt++) {
                const int c0 = j0 + nt * 8 + tg * 2;
                if (c0     > rbase)     cS[nt][0] = -1e30f;
                if (c0 + 1 > rbase)     cS[nt][1] = -1e30f;
                if (c0     > rbase + 8) cS[nt][2] = -1e30f;
                if (c0 + 1 > rbase + 8) cS[nt][3] = -1e30f;
            }
        }

        // ---- online softmax per row (rows g and g+8; reduce over quad) ----
        float* pb = sP + (w * 16) * ASTR;
#pragma unroll
        for (int rh = 0; rh < 2; rh++) {
            float mx = -1e30f;
#pragma unroll
            for (int nt = 0; nt < 8; nt++)
                mx = fmaxf(mx, fmaxf(cS[nt][2 * rh], cS[nt][2 * rh + 1]));
            mx = fmaxf(mx, __shfl_xor_sync(0xffffffffu, mx, 1));
            mx = fmaxf(mx, __shfl_xor_sync(0xffffffffu, mx, 2));
            const float mnew = fmaxf(mrow[rh], mx);
            const float corr = __expf(mrow[rh] - mnew);
            float sum = 0.f;
#pragma unroll
            for (int nt = 0; nt < 8; nt++) {
                float p0 = __expf(cS[nt][2 * rh]     - mnew);
                float p1 = __expf(cS[nt][2 * rh + 1] - mnew);
                cS[nt][2 * rh]     = p0;
                cS[nt][2 * rh + 1] = p1;
                sum += p0 + p1;
            }
            sum += __shfl_xor_sync(0xffffffffu, sum, 1);
            sum += __shfl_xor_sync(0xffffffffu, sum, 2);
            lrow[rh] = lrow[rh] * corr + sum;
            mrow[rh] = mnew;
#pragma unroll
            for (int nt = 0; nt < 8; nt++) {
                cO[nt][2 * rh]     *= corr;
                cO[nt][2 * rh + 1] *= corr;
            }
            // write P (tf32) to this warp's slab
            float* prow = pb + (g + 8 * rh) * ASTR;
#pragma unroll
            for (int nt = 0; nt < 8; nt++) {
                float2 pv;
                pv.x = f2tf32(cS[nt][2 * rh]);
                pv.y = f2tf32(cS[nt][2 * rh + 1]);
                *(float2*)(prow + nt * 8 + tg * 2) = pv;
            }
        }
        __syncwarp();

        // ---- O += P @ V : A frag from sP, B frag from sV[key][d] ----
#pragma unroll
        for (int kk = 0; kk < 8; kk++) {
            unsigned aP[4];
            aP[0] = __float_as_uint(pb[g * ASTR + kk * 8 + tg]);
            aP[1] = __float_as_uint(pb[(g + 8) * ASTR + kk * 8 + tg]);
            aP[2] = __float_as_uint(pb[g * ASTR + kk * 8 + tg + 4]);
            aP[3] = __float_as_uint(pb[(g + 8) * ASTR + kk * 8 + tg + 4]);
#pragma unroll
            for (int nt = 0; nt < 8; nt++) {
                const float* vp0 = sV + (kk * 8 + tg) * ASTR + nt * 8 + g;
                const float* vp1 = sV + (kk * 8 + tg + 4) * ASTR + nt * 8 + g;
                unsigned b0 = __float_as_uint(vp0[0]);
                unsigned b1 = __float_as_uint(vp1[0]);
                MMA_TF32(cO[nt], aP, b0, b1);
            }
        }
    }

    // ---- epilogue: normalize and store (folds head transpose) ----
    const float inv0 = 1.f / lrow[0];
    const float inv1 = 1.f / lrow[1];
    const int r0 = q0 + w * 16 + g;
    float* o0p = O + (size_t)(b * SEQ + r0) * DMODEL + h * HDIM;
    float* o1p = O + (size_t)(b * SEQ + r0 + 8) * DMODEL + h * HDIM;
#pragma unroll
    for (int nt = 0; nt < 8; nt++) {
        const int c = nt * 8 + tg * 2;
        float2 v0, v1;
        v0.x = cO[nt][0] * inv0; v0.y = cO[nt][1] * inv0;
        v1.x = cO[nt][2] * inv1; v1.y = cO[nt][3] * inv1;
        *(float2*)(o0p + c) = v0;
        *(float2*)(o1p + c) = v1;
    }
}

// ----------------------------------------------------------------------------
// LayerNorm (unchanged)
// ----------------------------------------------------------------------------
__global__ __launch_bounds__(256) void ln_kernel(
    const float* __restrict__ X, const float* __restrict__ g,
    const float* __restrict__ bb, float* __restrict__ Y)
{
    __shared__ float red[16];
    const int row = blockIdx.x;
    const int tid = threadIdx.x;
    const float4 xv = *(const float4*)(X + (size_t)row * DMODEL + tid * 4);

    float s  = xv.x + xv.y + xv.z + xv.w;
    float sq = xv.x*xv.x + xv.y*xv.y + xv.z*xv.z + xv.w*xv.w;
#pragma unroll
    for (int off = 16; off > 0; off >>= 1) {
        s  += __shfl_xor_sync(0xffffffffu, s,  off);
        sq += __shfl_xor_sync(0xffffffffu, sq, off);
    }
    const int warp = tid >> 5, lane = tid & 31;
    if (lane == 0) { red[warp] = s; red[warp + 8] = sq; }
    __syncthreads();
    if (warp == 0) {
        float a = (lane < 8) ? red[lane] : 0.f;
        float c = (lane < 8) ? red[lane + 8] : 0.f;
#pragma unroll
        for (int off = 4; off > 0; off >>= 1) {
            a += __shfl_xor_sync(0xffffffffu, a, off);
            c += __shfl_xor_sync(0xffffffffu, c, off);
        }
        if (lane == 0) { red[0] = a; red[1] = c; }
    }
    __syncthreads();
    const float mu  = red[0] * (1.f / DMODEL);
    const float var = red[1] * (1.f / DMODEL) - mu * mu;
    const float rstd = rsqrtf(var + LN_EPS);

    const float4 gv = *(const float4*)(g  + tid * 4);
    const float4 bv = *(const float4*)(bb + tid * 4);
    float4 yv;
    yv.x = (xv.x - mu) * rstd * gv.x + bv.x;
    yv.y = (xv.y - mu) * rstd * gv.y + bv.y;
    yv.z = (xv.z - mu) * rstd * gv.z + bv.z;
    yv.w = (xv.w - mu) * rstd * gv.w + bv.w;
    *(float4*)(Y + (size_t)row * DMODEL + tid * 4) = yv;
}

// ----------------------------------------------------------------------------
// Launch
// ----------------------------------------------------------------------------
extern "C" void kernel_launch(void* const* d_in, const int* in_sizes, int n_in,
                              void* d_out, int out_size)
{
    const float* x    = (const float*)d_in[0];
    const float* enc  = (const float*)d_in[1];
    const float* s_wq = (const float*)d_in[2];  const float* s_bq = (const float*)d_in[3];
    const float* s_wk = (const float*)d_in[4];  const float* s_bk = (const float*)d_in[5];
    const float* s_wv = (const float*)d_in[6];  const float* s_bv = (const float*)d_in[7];
    const float* s_wo = (const float*)d_in[8];  const float* s_bo = (const float*)d_in[9];
    const float* c_wq = (const float*)d_in[10]; const float* c_bq = (const float*)d_in[11];
    const float* c_wk = (const float*)d_in[12]; const float* c_bk = (const float*)d_in[13];
    const float* c_wv = (const float*)d_in[14]; const float* c_bv = (const float*)d_in[15];
    const float* c_wo = (const float*)d_in[16]; const float* c_bo = (const float*)d_in[17];
    const float* f_w1 = (const float*)d_in[18]; const float* f_b1 = (const float*)d_in[19];
    const float* f_w2 = (const float*)d_in[20]; const float* f_b2 = (const float*)d_in[21];
    const float* ln1g = (const float*)d_in[22]; const float* ln1b = (const float*)d_in[23];
    const float* ln2g = (const float*)d_in[24]; const float* ln2b = (const float*)d_in[25];
    const float* ln3g = (const float*)d_in[26]; const float* ln3b = (const float*)d_in[27];
    float* out = (float*)d_out;

    float *q, *k, *v, *attn, *tmp, *y1, *y2, *ffn;
    cudaGetSymbolAddress((void**)&q,    g_q);
    cudaGetSymbolAddress((void**)&k,    g_k);
    cudaGetSymbolAddress((void**)&v,    g_v);
    cudaGetSymbolAddress((void**)&attn, g_attn);
    cudaGetSymbolAddress((void**)&tmp,  g_tmp);
    cudaGetSymbolAddress((void**)&y1,   g_y1);
    cudaGetSymbolAddress((void**)&y2,   g_y2);
    cudaGetSymbolAddress((void**)&ffn,  g_ffn);

    cudaFuncSetAttribute(attn_tc<true>,
        cudaFuncAttributeMaxDynamicSharedMemorySize, ATT_SMEM);
    cudaFuncSetAttribute(attn_tc<false>,
        cudaFuncAttributeMaxDynamicSharedMemorySize, ATT_SMEM);

    const dim3 blk(256);
    const dim3 ablk(128);
    const dim3 gatt(SEQ / 64, NHEADS, BATCH);
    const dim3 gln(TOK);

    GemmArgs ga;

    // ---- self attention: fused QKV projection (z=3) ----
    ga = GemmArgs{};
    ga.A[0] = x;    ga.A[1] = x;    ga.A[2] = x;
    ga.W[0] = s_wq; ga.W[1] = s_wk; ga.W[2] = s_wv;
    ga.bias[0] = s_bq; ga.bias[1] = s_bk; ga.bias[2] = s_bv;
    ga.R[0] = x; ga.R[1] = x; ga.R[2] = x;
    ga.C[0] = q; ga.C[1] = k; ga.C[2] = v;
    ga.N = DMODEL; ga.K = DMODEL;
    gemm_tf32<false,false><<<dim3(DMODEL/128, TOK/128, 3), blk>>>(ga);

    attn_tc<true><<<gatt, ablk, ATT_SMEM>>>(q, k, v, attn);

    ga.A[0] = attn; ga.W[0] = s_wo; ga.bias[0] = s_bo; ga.R[0] = x; ga.C[0] = tmp;
    gemm_tf32<false,true><<<dim3(DMODEL/128, TOK/128, 1), blk>>>(ga);
    ln_kernel<<<gln, blk>>>(tmp, ln1g, ln1b, y1);

    // ---- cross attention: fused Q(y1) + K,V(enc) projection (z=3) ----
    ga.A[0] = y1;   ga.A[1] = enc;  ga.A[2] = enc;
    ga.W[0] = c_wq; ga.W[1] = c_wk; ga.W[2] = c_wv;
    ga.bias[0] = c_bq; ga.bias[1] = c_bk; ga.bias[2] = c_bv;
    ga.R[0] = x; ga.R[1] = x; ga.R[2] = x;
    ga.C[0] = q; ga.C[1] = k; ga.C[2] = v;
    gemm_tf32<false,false><<<dim3(DMODEL/128, TOK/128, 3), blk>>>(ga);

    attn_tc<false><<<gatt, ablk, ATT_SMEM>>>(q, k, v, attn);

    ga.A[0] = attn; ga.W[0] = c_wo; ga.bias[0] = c_bo; ga.R[0] = y1; ga.C[0] = tmp;
    gemm_tf32<false,true><<<dim3(DMODEL/128, TOK/128, 1), blk>>>(ga);
    ln_kernel<<<gln, blk>>>(tmp, ln2g, ln2b, y2);

    // ---- FFN ----
    ga.A[0] = y2; ga.W[0] = f_w1; ga.bias[0] = f_b1; ga.R[0] = x; ga.C[0] = ffn;
    ga.N = DFF; ga.K = DMODEL;
    gemm_tf32<true,false><<<dim3(DFF/128, TOK/128, 1), blk>>>(ga);

    ga.A[0] = ffn; ga.W[0] = f_w2; ga.bias[0] = f_b2; ga.R[0] = y2; ga.C[0] = tmp;
    ga.N = DMODEL; ga.K = DFF;
    gemm_tf32<false,true><<<dim3(DMODEL/128, TOK/128, 1), blk>>>(ga);
    ln_kernel<<<gln, blk>>>(tmp, ln3g, ln3b, out);
}